// round 8
// baseline (speedup 1.0000x reference)
#include <cuda_runtime.h>
#include <cub/cub.cuh>

// ---------------- problem constants ----------------
namespace {
constexpr int   F      = 64;
constexpr int   NXc    = 65;
constexpr int   NYc    = 87;
constexpr int   Vc     = NXc * NYc;   // 5655
constexpr int   Bc     = 8;
constexpr int   Sc     = Bc * Vc;     // 45240  (< 2^16)
constexpr int   NMAX   = 1000000;
constexpr int   EMAX   = 8000000;
constexpr float VOXELf = 4.0f;
constexpr int   BCAP   = 4096;        // per-bucket smem capacity (avg 177, max ~450)
}

// ---------------- static device scratch (no allocs allowed) ----------------
__device__ unsigned short g_cluster16[NMAX];
__device__ int            g_count[Sc];
__device__ unsigned       g_keys_in[EMAX];
__device__ unsigned short g_cbuf[EMAX];     // bucketed c values
__device__ int            g_bcount[Sc];     // edges per r-bucket
__device__ int            g_boffset[Sc];    // exclusive scan
__device__ int            g_cursor[Sc];     // scatter cursors

// ---------------- host-side streams/events (host objects only) ----------
struct StreamPack {
    cudaStream_t s2 = nullptr;
    cudaEvent_t  ev_fork = nullptr, ev_join = nullptr;
    StreamPack() {
        cudaStreamCreateWithFlags(&s2, cudaStreamNonBlocking);
        cudaEventCreateWithFlags(&ev_fork, cudaEventDisableTiming);
        cudaEventCreateWithFlags(&ev_join, cudaEventDisableTiming);
    }
};
static StreamPack g_sp;

// ---------------- order-preserving f32 <-> u32 ----------------
__device__ __forceinline__ unsigned f2ord(float f) {
    unsigned u = __float_as_uint(f);
    unsigned m = (unsigned)((int)u >> 31);
    return u ^ (m | 0x80000000u);
}
__device__ __forceinline__ float ord2f(unsigned u) {
    unsigned bits = (u & 0x80000000u) ? (u ^ 0x80000000u) : ~u;
    return __uint_as_float(bits);
}

// ---------------- kernels ----------------

// init: x_pool -> ord sentinel 0, pos -> 0, counters -> 0, batch_out
__global__ void k_init(float* __restrict__ out) {
    int i = blockIdx.x * blockDim.x + threadIdx.x;
    if (i < Sc * F) ((unsigned*)out)[i] = 0u;
    if (i < Sc * 3) out[Sc * F + i] = 0.0f;
    if (i < Sc) {
        out[Sc * F + Sc * 3 + i] = (float)(i / Vc);   // batch_out
        g_count[i]  = 0;
        g_bcount[i] = 0;
    }
}

// cluster assignment + pos sums + counts
__global__ void k_cluster(const float* __restrict__ pos,
                          const int* __restrict__ batch,
                          float* __restrict__ pos_out, int N) {
    int i = blockIdx.x * blockDim.x + threadIdx.x;
    if (i >= N) return;
    float px = pos[3 * i + 0];
    float py = pos[3 * i + 1];
    float pt = pos[3 * i + 2];
    int c0 = (int)floorf(px / VOXELf); c0 = min(max(c0, 0), NXc - 1);
    int c1 = (int)floorf(py / VOXELf); c1 = min(max(c1, 0), NYc - 1);
    int cl = batch[i] * Vc + c0 * NYc + c1;
    g_cluster16[i] = (unsigned short)cl;
    atomicAdd(&pos_out[cl * 3 + 0], px);
    atomicAdd(&pos_out[cl * 3 + 1], py);
    atomicAdd(&pos_out[cl * 3 + 2], pt);
    atomicAdd(&g_count[cl], 1);
}

// x scatter-max: u32 RED.MAX on ord-encoded values
__global__ void k_xmax(const float4* __restrict__ x4,
                       unsigned* __restrict__ xp, int N) {
    int i = blockIdx.x * blockDim.x + threadIdx.x;
    int total = N * (F / 4);
    if (i >= total) return;
    int node = i >> 4;
    int q    = (i & 15) << 2;
    float4 v = x4[i];
    unsigned* addr = xp + (int)g_cluster16[node] * F + q;
    atomicMax(addr + 0, f2ord(v.x));
    atomicMax(addr + 1, f2ord(v.y));
    atomicMax(addr + 2, f2ord(v.z));
    atomicMax(addr + 3, f2ord(v.w));
}

// edge keys (r<<16|c) + fused r-histogram
__global__ void k_edgekey(const int* __restrict__ ei, int E) {
    int i = blockIdx.x * blockDim.x + threadIdx.x;
    int E4 = E >> 2;
    if (i < E4) {
        int4 a = ((const int4*)ei)[i];
        int4 b = ((const int4*)(ei + E))[i];
        unsigned r0 = g_cluster16[a.x], r1 = g_cluster16[a.y];
        unsigned r2 = g_cluster16[a.z], r3 = g_cluster16[a.w];
        uint4 k;
        k.x = (r0 << 16) | g_cluster16[b.x];
        k.y = (r1 << 16) | g_cluster16[b.y];
        k.z = (r2 << 16) | g_cluster16[b.z];
        k.w = (r3 << 16) | g_cluster16[b.w];
        ((uint4*)g_keys_in)[i] = k;
        atomicAdd(&g_bcount[r0], 1);
        atomicAdd(&g_bcount[r1], 1);
        atomicAdd(&g_bcount[r2], 1);
        atomicAdd(&g_bcount[r3], 1);
    }
    int t = E4 * 4 + i;
    if (i < (E & 3) && t < E) {
        unsigned r = g_cluster16[ei[t]];
        g_keys_in[t] = (r << 16) | g_cluster16[ei[E + t]];
        atomicAdd(&g_bcount[r], 1);
    }
}

// single-block exclusive scan of g_bcount -> g_boffset, g_cursor
__global__ void k_scan() {
    typedef cub::BlockScan<int, 1024> BS;
    __shared__ typename BS::TempStorage ts;
    __shared__ int carry;
    if (threadIdx.x == 0) carry = 0;
    __syncthreads();
    for (int base = 0; base < Sc; base += 1024) {
        int i = base + threadIdx.x;
        int v = (i < Sc) ? g_bcount[i] : 0;
        int ex, tot;
        BS(ts).ExclusiveSum(v, ex, tot);
        __syncthreads();
        int o = carry + ex;                    // read carry (stable here)
        if (i < Sc) { g_boffset[i] = o; g_cursor[i] = o; }
        __syncthreads();
        if (threadIdx.x == 0) carry += tot;
        __syncthreads();
    }
}

// scatter c values into r-buckets
__global__ void k_scatter(int E) {
    int i = blockIdx.x * blockDim.x + threadIdx.x;
    if (i >= E) return;
    unsigned k = g_keys_in[i];
    int r = (int)(k >> 16);
    int p = atomicAdd(&g_cursor[r], 1);
    g_cbuf[p] = (unsigned short)(k & 0xFFFFu);
}

// per-bucket rank sort + fused edge emission (dedup + self-loop -> -1)
__global__ void k_bsort(float* __restrict__ er, int E) {
    __shared__ unsigned short sc[BCAP];
    int r     = blockIdx.x;
    int n     = g_bcount[r];
    int start = g_boffset[r];
    if (n <= 0) return;
    if (n > BCAP) n = BCAP;   // statistically unreachable (max ~450)
    for (int j = threadIdx.x; j < n; j += blockDim.x)
        sc[j] = g_cbuf[start + j];
    __syncthreads();
    unsigned short ru = (unsigned short)r;
    for (int j = threadIdx.x; j < n; j += blockDim.x) {
        unsigned short v = sc[j];
        int rank = 0, eqb = 0;
        for (int i2 = 0; i2 < n; ++i2) {
            unsigned short w = sc[i2];
            rank += (w < v);
            eqb  += (w == v) & (i2 < j);
        }
        int posn = start + rank + eqb;           // stable global sorted position
        bool valid = (eqb == 0) && (v != ru);    // first of run, not self-loop
        er[posn]     = valid ? (float)r : -1.0f;
        er[E + posn] = valid ? (float)v : -1.0f;
    }
}

// finalize: decode ord->float (0 for empty), divide pos sums, write mask
__global__ void k_final(float* __restrict__ out, int E) {
    int i = blockIdx.x * blockDim.x + threadIdx.x;
    if (i < Sc * F) {
        int cl = i >> 6;
        unsigned u = ((unsigned*)out)[i];
        out[i] = (g_count[cl] == 0) ? 0.0f : ord2f(u);
    }
    if (i < Sc * 3) {
        int cl = i / 3;
        float cnt = (float)g_count[cl];
        out[Sc * F + i] = out[Sc * F + i] / fmaxf(cnt, 1.0f);
    }
    if (i < Sc) {
        out[Sc * F + Sc * 3 + Sc + 2 * E + i] = (g_count[i] > 0) ? 1.0f : 0.0f;
    }
}

// ---------------- launch ----------------
extern "C" void kernel_launch(void* const* d_in, const int* in_sizes, int n_in,
                              void* d_out, int out_size) {
    const float* x     = (const float*)d_in[0];
    const float* pos   = (const float*)d_in[1];
    const int*   batch = (const int*)d_in[2];
    const int*   ei    = (const int*)d_in[3];
    float* out = (float*)d_out;

    int N = in_sizes[2];
    int E = in_sizes[3] / 2;

    constexpr int T = 256;
    cudaStream_t s0 = 0;
    cudaStream_t s2 = g_sp.s2;

    // serial head (both paths depend on these)
    k_init<<<(Sc * F + T - 1) / T, T, 0, s0>>>(out);
    k_cluster<<<(N + T - 1) / T, T, 0, s0>>>(pos, batch, out + Sc * F, N);

    // fork: edge path on s2
    cudaEventRecord(g_sp.ev_fork, s0);
    cudaStreamWaitEvent(s2, g_sp.ev_fork, 0);

    float* edge_out = out + Sc * F + Sc * 3 + Sc;
    k_edgekey<<<((E >> 2) + T - 1) / T, T, 0, s2>>>(ei, E);
    k_scan<<<1, 1024, 0, s2>>>();
    k_scatter<<<(E + T - 1) / T, T, 0, s2>>>(E);
    k_bsort<<<Sc, 128, 0, s2>>>(edge_out, E);
    cudaEventRecord(g_sp.ev_join, s2);

    // x path on main stream
    k_xmax<<<(N * (F / 4) + T - 1) / T, T, 0, s0>>>((const float4*)x,
                                                    (unsigned*)out, N);
    k_final<<<(Sc * F + T - 1) / T, T, 0, s0>>>(out, E);

    // join
    cudaStreamWaitEvent(s0, g_sp.ev_join, 0);
}

// round 9
// speedup vs baseline: 1.5867x; 1.5867x over previous
#include <cuda_runtime.h>
#include <cub/cub.cuh>

// ---------------- problem constants ----------------
namespace {
constexpr int   F      = 64;
constexpr int   NXc    = 65;
constexpr int   NYc    = 87;
constexpr int   Vc     = NXc * NYc;   // 5655
constexpr int   Bc     = 8;
constexpr int   Sc     = Bc * Vc;     // 45240  (< 2^16)
constexpr int   NMAX   = 1000000;
constexpr int   EMAX   = 8000000;
constexpr float VOXELf = 4.0f;
constexpr int   BSORT_T    = 128;     // bsort threads
constexpr int   BSORT_I    = 4;       // items/thread
constexpr int   BSORT_CAP  = BSORT_T * BSORT_I;  // 512 (max bucket ~450)
}

// ---------------- static device scratch (no allocs allowed) ----------------
__device__ unsigned short g_cluster16[NMAX];
__device__ int            g_count[Sc];
__device__ unsigned       g_keys_in[EMAX];
__device__ unsigned short g_cbuf[EMAX];     // bucketed c values
__device__ int            g_bcount[Sc];     // edges per r-bucket
__device__ int            g_boffset[Sc];    // excl scan; advanced to end by scatter
__device__ unsigned char  g_temp[4u * 1024u * 1024u];   // DeviceScan temp

// ---------------- host-side streams/events (host objects only) ----------
struct StreamPack {
    cudaStream_t s2 = nullptr;
    cudaEvent_t  ev_fork = nullptr, ev_join = nullptr;
    StreamPack() {
        cudaStreamCreateWithFlags(&s2, cudaStreamNonBlocking);
        cudaEventCreateWithFlags(&ev_fork, cudaEventDisableTiming);
        cudaEventCreateWithFlags(&ev_join, cudaEventDisableTiming);
    }
};
static StreamPack g_sp;

// ---------------- order-preserving f32 <-> u32 ----------------
__device__ __forceinline__ unsigned f2ord(float f) {
    unsigned u = __float_as_uint(f);
    unsigned m = (unsigned)((int)u >> 31);
    return u ^ (m | 0x80000000u);
}
__device__ __forceinline__ float ord2f(unsigned u) {
    unsigned bits = (u & 0x80000000u) ? (u ^ 0x80000000u) : ~u;
    return __uint_as_float(bits);
}

// ---------------- kernels ----------------

__global__ void k_init(float* __restrict__ out) {
    int i = blockIdx.x * blockDim.x + threadIdx.x;
    if (i < Sc * F) ((unsigned*)out)[i] = 0u;            // ord sentinel
    if (i < Sc * 3) out[Sc * F + i] = 0.0f;
    if (i < Sc) {
        out[Sc * F + Sc * 3 + i] = (float)(i / Vc);      // batch_out
        g_count[i]  = 0;
        g_bcount[i] = 0;
    }
}

__global__ void k_cluster(const float* __restrict__ pos,
                          const int* __restrict__ batch,
                          float* __restrict__ pos_out, int N) {
    int i = blockIdx.x * blockDim.x + threadIdx.x;
    if (i >= N) return;
    float px = pos[3 * i + 0];
    float py = pos[3 * i + 1];
    float pt = pos[3 * i + 2];
    int c0 = (int)floorf(px / VOXELf); c0 = min(max(c0, 0), NXc - 1);
    int c1 = (int)floorf(py / VOXELf); c1 = min(max(c1, 0), NYc - 1);
    int cl = batch[i] * Vc + c0 * NYc + c1;
    g_cluster16[i] = (unsigned short)cl;
    atomicAdd(&pos_out[cl * 3 + 0], px);
    atomicAdd(&pos_out[cl * 3 + 1], py);
    atomicAdd(&pos_out[cl * 3 + 2], pt);
    atomicAdd(&g_count[cl], 1);
}

__global__ void k_xmax(const float4* __restrict__ x4,
                       unsigned* __restrict__ xp, int N) {
    int i = blockIdx.x * blockDim.x + threadIdx.x;
    int total = N * (F / 4);
    if (i >= total) return;
    int node = i >> 4;
    int q    = (i & 15) << 2;
    float4 v = x4[i];
    unsigned* addr = xp + (int)g_cluster16[node] * F + q;
    atomicMax(addr + 0, f2ord(v.x));
    atomicMax(addr + 1, f2ord(v.y));
    atomicMax(addr + 2, f2ord(v.z));
    atomicMax(addr + 3, f2ord(v.w));
}

// edge keys (r<<16|c) + fused r-histogram
__global__ void k_edgekey(const int* __restrict__ ei, int E) {
    int i = blockIdx.x * blockDim.x + threadIdx.x;
    int E4 = E >> 2;
    if (i < E4) {
        int4 a = ((const int4*)ei)[i];
        int4 b = ((const int4*)(ei + E))[i];
        unsigned r0 = g_cluster16[a.x], r1 = g_cluster16[a.y];
        unsigned r2 = g_cluster16[a.z], r3 = g_cluster16[a.w];
        uint4 k;
        k.x = (r0 << 16) | g_cluster16[b.x];
        k.y = (r1 << 16) | g_cluster16[b.y];
        k.z = (r2 << 16) | g_cluster16[b.z];
        k.w = (r3 << 16) | g_cluster16[b.w];
        ((uint4*)g_keys_in)[i] = k;
        atomicAdd(&g_bcount[r0], 1);
        atomicAdd(&g_bcount[r1], 1);
        atomicAdd(&g_bcount[r2], 1);
        atomicAdd(&g_bcount[r3], 1);
    }
    int t = E4 * 4 + i;
    if (i < (E & 3) && t < E) {
        unsigned r = g_cluster16[ei[t]];
        g_keys_in[t] = (r << 16) | g_cluster16[ei[E + t]];
        atomicAdd(&g_bcount[r], 1);
    }
}

// scatter c values into r-buckets; advances g_boffset[r] to bucket end
__global__ void k_scatter(int E) {
    int i = blockIdx.x * blockDim.x + threadIdx.x;
    if (i >= E) return;
    unsigned k = g_keys_in[i];
    int r = (int)(k >> 16);
    int p = atomicAdd(&g_boffset[r], 1);
    g_cbuf[p] = (unsigned short)(k & 0xFFFFu);
}

// per-bucket cub BlockRadixSort + fused edge emission (dedup + self-loop -> -1)
__global__ void __launch_bounds__(BSORT_T)
k_bsort(float* __restrict__ er, int E) {
    typedef cub::BlockRadixSort<unsigned short, BSORT_T, BSORT_I> BRS;
    __shared__ union {
        typename BRS::TempStorage sort;
        unsigned short sorted[BSORT_CAP];
    } sh;
    int r = blockIdx.x;
    int n = g_bcount[r];
    if (n <= 0) return;
    int start = g_boffset[r] - n;     // boffset now points at bucket end
    if (n > BSORT_CAP) n = BSORT_CAP; // statistically unreachable (max ~450)

    unsigned short keys[BSORT_I];
    #pragma unroll
    for (int k = 0; k < BSORT_I; ++k) {
        int j = threadIdx.x * BSORT_I + k;    // blocked arrangement
        keys[k] = (j < n) ? g_cbuf[start + j] : (unsigned short)0xFFFFu;
    }
    BRS(sh.sort).Sort(keys);
    __syncthreads();
    #pragma unroll
    for (int k = 0; k < BSORT_I; ++k)
        sh.sorted[threadIdx.x * BSORT_I + k] = keys[k];
    __syncthreads();

    unsigned short ru = (unsigned short)r;
    for (int j = threadIdx.x; j < n; j += BSORT_T) {
        unsigned short v = sh.sorted[j];
        unsigned short p = (j == 0) ? (unsigned short)0xFFFFu : sh.sorted[j - 1];
        bool valid = (v != p) && (v != ru);
        er[start + j]     = valid ? (float)r : -1.0f;
        er[E + start + j] = valid ? (float)v : -1.0f;
    }
}

// finalize: decode ord->float (0 for empty), divide pos sums, write mask
__global__ void k_final(float* __restrict__ out, int E) {
    int i = blockIdx.x * blockDim.x + threadIdx.x;
    if (i < Sc * F) {
        int cl = i >> 6;
        unsigned u = ((unsigned*)out)[i];
        out[i] = (g_count[cl] == 0) ? 0.0f : ord2f(u);
    }
    if (i < Sc * 3) {
        int cl = i / 3;
        float cnt = (float)g_count[cl];
        out[Sc * F + i] = out[Sc * F + i] / fmaxf(cnt, 1.0f);
    }
    if (i < Sc) {
        out[Sc * F + Sc * 3 + Sc + 2 * E + i] = (g_count[i] > 0) ? 1.0f : 0.0f;
    }
}

// ---------------- launch ----------------
extern "C" void kernel_launch(void* const* d_in, const int* in_sizes, int n_in,
                              void* d_out, int out_size) {
    const float* x     = (const float*)d_in[0];
    const float* pos   = (const float*)d_in[1];
    const int*   batch = (const int*)d_in[2];
    const int*   ei    = (const int*)d_in[3];
    float* out = (float*)d_out;

    int N = in_sizes[2];
    int E = in_sizes[3] / 2;

    void *p_bcount, *p_boffset, *p_temp;
    cudaGetSymbolAddress(&p_bcount,  g_bcount);
    cudaGetSymbolAddress(&p_boffset, g_boffset);
    cudaGetSymbolAddress(&p_temp,    g_temp);

    constexpr int T = 256;
    cudaStream_t s0 = 0;
    cudaStream_t s2 = g_sp.s2;

    // serial head (both paths depend on these)
    k_init<<<(Sc * F + T - 1) / T, T, 0, s0>>>(out);
    k_cluster<<<(N + T - 1) / T, T, 0, s0>>>(pos, batch, out + Sc * F, N);

    // fork: edge path on s2
    cudaEventRecord(g_sp.ev_fork, s0);
    cudaStreamWaitEvent(s2, g_sp.ev_fork, 0);

    float* edge_out = out + Sc * F + Sc * 3 + Sc;
    k_edgekey<<<((E >> 2) + T - 1) / T, T, 0, s2>>>(ei, E);

    size_t temp_bytes = 0;
    cub::DeviceScan::ExclusiveSum(nullptr, temp_bytes,
                                  (const int*)p_bcount, (int*)p_boffset, Sc, s2);
    if (temp_bytes > sizeof(g_temp)) temp_bytes = sizeof(g_temp);
    cub::DeviceScan::ExclusiveSum(p_temp, temp_bytes,
                                  (const int*)p_bcount, (int*)p_boffset, Sc, s2);

    k_scatter<<<(E + T - 1) / T, T, 0, s2>>>(E);
    k_bsort<<<Sc, BSORT_T, 0, s2>>>(edge_out, E);
    cudaEventRecord(g_sp.ev_join, s2);

    // x path on main stream
    k_xmax<<<(N * (F / 4) + T - 1) / T, T, 0, s0>>>((const float4*)x,
                                                    (unsigned*)out, N);
    k_final<<<(Sc * F + T - 1) / T, T, 0, s0>>>(out, E);

    // join
    cudaStreamWaitEvent(s0, g_sp.ev_join, 0);
}

// round 14
// speedup vs baseline: 2.5217x; 1.5893x over previous
#include <cuda_runtime.h>
#include <cub/cub.cuh>

// ---------------- problem constants ----------------
namespace {
constexpr int   F      = 64;
constexpr int   NXc    = 65;
constexpr int   NYc    = 87;
constexpr int   Vc     = NXc * NYc;   // 5655
constexpr int   Bc     = 8;
constexpr int   Sc     = Bc * Vc;     // 45240  (< 2^16)
constexpr int   NMAX   = 1000000;
constexpr int   EMAX   = 8000000;
constexpr float VOXELf = 4.0f;
}

// ---------------- static device scratch (no allocs allowed) ----------------
__device__ unsigned short g_cluster16[NMAX];
__device__ int            g_nodeidx[NMAX];   // nodes bucketed by cluster
__device__ int            g_count[Sc];
__device__ int            g_noffset[Sc];     // excl scan of count; advanced to end
__device__ unsigned       g_keys_in[EMAX];
__device__ unsigned       g_keys_out[EMAX];
__device__ unsigned char  g_temp[160u * 1024u * 1024u];   // cub radix temp
__device__ unsigned char  g_temp2[1u * 1024u * 1024u];    // cub scan temp

// ---------------- host-side streams/events (host objects only) ----------
struct StreamPack {
    cudaStream_t s2 = nullptr;
    cudaEvent_t  ev_fork = nullptr, ev_join = nullptr;
    StreamPack() {
        cudaStreamCreateWithFlags(&s2, cudaStreamNonBlocking);
        cudaEventCreateWithFlags(&ev_fork, cudaEventDisableTiming);
        cudaEventCreateWithFlags(&ev_join, cudaEventDisableTiming);
    }
};
static StreamPack g_sp;

// ---------------- kernels ----------------

// init: pos region -> 0, counters -> 0, batch_out written
__global__ void k_init(float* __restrict__ out) {
    int i = blockIdx.x * blockDim.x + threadIdx.x;
    if (i < Sc * 3) out[Sc * F + i] = 0.0f;
    if (i < Sc) {
        out[Sc * F + Sc * 3 + i] = (float)(i / Vc);      // batch_out
        g_count[i] = 0;
    }
}

// cluster assignment + pos sums + counts
__global__ void k_cluster(const float* __restrict__ pos,
                          const int* __restrict__ batch,
                          float* __restrict__ pos_out, int N) {
    int i = blockIdx.x * blockDim.x + threadIdx.x;
    if (i >= N) return;
    float px = pos[3 * i + 0];
    float py = pos[3 * i + 1];
    float pt = pos[3 * i + 2];
    int c0 = (int)floorf(px / VOXELf); c0 = min(max(c0, 0), NXc - 1);
    int c1 = (int)floorf(py / VOXELf); c1 = min(max(c1, 0), NYc - 1);
    int cl = batch[i] * Vc + c0 * NYc + c1;
    g_cluster16[i] = (unsigned short)cl;
    atomicAdd(&pos_out[cl * 3 + 0], px);
    atomicAdd(&pos_out[cl * 3 + 1], py);
    atomicAdd(&pos_out[cl * 3 + 2], pt);
    atomicAdd(&g_count[cl], 1);
}

// bucket node indices by cluster (advances g_noffset[cl] to bucket end)
__global__ void k_nscatter(int N) {
    int i = blockIdx.x * blockDim.x + threadIdx.x;
    if (i >= N) return;
    int cl = (int)g_cluster16[i];
    int p = atomicAdd(&g_noffset[cl], 1);
    g_nodeidx[p] = i;
}

// gather-max: one warp per cluster, lane f and f+32; zero atomics
__global__ void k_xmax_gather(const float* __restrict__ x,
                              float* __restrict__ xp) {
    int w = (blockIdx.x * blockDim.x + threadIdx.x) >> 5;
    if (w >= Sc) return;
    int lane  = threadIdx.x & 31;
    int n     = g_count[w];
    int start = g_noffset[w] - n;    // noffset points at bucket end
    float m0 = -__int_as_float(0x7F800000);   // -inf
    float m1 = m0;
    int j = 0;
    for (; j + 2 <= n; j += 2) {     // 2-way unroll for MLP
        const float* ra = x + (size_t)g_nodeidx[start + j]     * F;
        const float* rb = x + (size_t)g_nodeidx[start + j + 1] * F;
        float a0 = ra[lane], a1 = ra[lane + 32];
        float b0 = rb[lane], b1 = rb[lane + 32];
        m0 = fmaxf(m0, fmaxf(a0, b0));
        m1 = fmaxf(m1, fmaxf(a1, b1));
    }
    if (j < n) {
        const float* ra = x + (size_t)g_nodeidx[start + j] * F;
        m0 = fmaxf(m0, ra[lane]);
        m1 = fmaxf(m1, ra[lane + 32]);
    }
    xp[w * F + lane]      = (n > 0) ? m0 : 0.0f;
    xp[w * F + lane + 32] = (n > 0) ? m1 : 0.0f;
}

// packed edge keys: key = (r<<16) | c — u32 order == lexsort(r,c)
__global__ void k_edgekey(const int* __restrict__ ei, int E) {
    int i = blockIdx.x * blockDim.x + threadIdx.x;
    int E4 = E >> 2;
    if (i < E4) {
        int4 a = ((const int4*)ei)[i];
        int4 b = ((const int4*)(ei + E))[i];
        uint4 k;
        k.x = ((unsigned)g_cluster16[a.x] << 16) | g_cluster16[b.x];
        k.y = ((unsigned)g_cluster16[a.y] << 16) | g_cluster16[b.y];
        k.z = ((unsigned)g_cluster16[a.z] << 16) | g_cluster16[b.z];
        k.w = ((unsigned)g_cluster16[a.w] << 16) | g_cluster16[b.w];
        ((uint4*)g_keys_in)[i] = k;
    }
    int t = E4 * 4 + i;
    if (i < (E & 3) && t < E) {
        g_keys_in[t] = ((unsigned)g_cluster16[ei[t]] << 16)
                     | g_cluster16[ei[E + t]];
    }
}

// emit sorted/deduped edges as float (-1 for dup or self-loop)
__global__ void k_edgeout(float* __restrict__ er, int E) {
    int i = blockIdx.x * blockDim.x + threadIdx.x;
    if (i >= E) return;
    unsigned k    = g_keys_out[i];
    unsigned prev = (i == 0) ? 0xFFFFFFFFu : g_keys_out[i - 1];
    unsigned r = k >> 16;
    unsigned c = k & 0xFFFFu;
    bool valid = (k != prev) && (r != c);
    er[i]     = valid ? (float)r : -1.0f;
    er[E + i] = valid ? (float)c : -1.0f;
}

// finalize: divide pos sums by count, write mask
__global__ void k_final(float* __restrict__ out, int E) {
    int i = blockIdx.x * blockDim.x + threadIdx.x;
    if (i < Sc * 3) {
        int cl = i / 3;
        float cnt = (float)g_count[cl];
        out[Sc * F + i] = out[Sc * F + i] / fmaxf(cnt, 1.0f);
    }
    if (i < Sc) {
        out[Sc * F + Sc * 3 + Sc + 2 * E + i] = (g_count[i] > 0) ? 1.0f : 0.0f;
    }
}

// ---------------- launch ----------------
extern "C" void kernel_launch(void* const* d_in, const int* in_sizes, int n_in,
                              void* d_out, int out_size) {
    const float* x     = (const float*)d_in[0];
    const float* pos   = (const float*)d_in[1];
    const int*   batch = (const int*)d_in[2];
    const int*   ei    = (const int*)d_in[3];
    float* out = (float*)d_out;

    int N = in_sizes[2];
    int E = in_sizes[3] / 2;

    void *p_kin, *p_kout, *p_temp, *p_count, *p_noff, *p_temp2;
    cudaGetSymbolAddress(&p_kin,   g_keys_in);
    cudaGetSymbolAddress(&p_kout,  g_keys_out);
    cudaGetSymbolAddress(&p_temp,  g_temp);
    cudaGetSymbolAddress(&p_count, g_count);
    cudaGetSymbolAddress(&p_noff,  g_noffset);
    cudaGetSymbolAddress(&p_temp2, g_temp2);

    constexpr int T = 256;
    cudaStream_t s0 = 0;
    cudaStream_t s2 = g_sp.s2;

    // serial head
    k_init<<<(Sc * 3 + T - 1) / T, T, 0, s0>>>(out);
    k_cluster<<<(N + T - 1) / T, T, 0, s0>>>(pos, batch, out + Sc * F, N);

    // fork: edge path on s2 (cub 32-bit radix — measured-fast path)
    cudaEventRecord(g_sp.ev_fork, s0);
    cudaStreamWaitEvent(s2, g_sp.ev_fork, 0);

    k_edgekey<<<((E >> 2) + T - 1) / T, T, 0, s2>>>(ei, E);
    size_t temp_bytes = 0;
    cub::DeviceRadixSort::SortKeys(nullptr, temp_bytes,
                                   (const unsigned*)p_kin, (unsigned*)p_kout,
                                   E, 0, 32, s2);
    if (temp_bytes > sizeof(g_temp)) temp_bytes = sizeof(g_temp);
    cub::DeviceRadixSort::SortKeys(p_temp, temp_bytes,
                                   (const unsigned*)p_kin, (unsigned*)p_kout,
                                   E, 0, 32, s2);
    k_edgeout<<<(E + T - 1) / T, T, 0, s2>>>(out + Sc * F + Sc * 3 + Sc, E);
    cudaEventRecord(g_sp.ev_join, s2);

    // x path on s0: bucket nodes, then gather-max (no atomics)
    size_t temp2_bytes = 0;
    cub::DeviceScan::ExclusiveSum(nullptr, temp2_bytes,
                                  (const int*)p_count, (int*)p_noff, Sc, s0);
    if (temp2_bytes > sizeof(g_temp2)) temp2_bytes = sizeof(g_temp2);
    cub::DeviceScan::ExclusiveSum(p_temp2, temp2_bytes,
                                  (const int*)p_count, (int*)p_noff, Sc, s0);
    k_nscatter<<<(N + T - 1) / T, T, 0, s0>>>(N);
    k_xmax_gather<<<(Sc * 32 + T - 1) / T, T, 0, s0>>>(x, out);
    k_final<<<(Sc * 3 + T - 1) / T, T, 0, s0>>>(out, E);

    // join
    cudaStreamWaitEvent(s0, g_sp.ev_join, 0);
}